// round 1
// baseline (speedup 1.0000x reference)
#include <cuda_runtime.h>

// Problem: mean_var_norm — (B=64, F=256, T=4000) fp32.
// Per (b,f) row: masked mean/var over t < n_b, normalize whole row.
// Single-pass: row lives in registers (4 x float4 per thread, 256 threads).

#define BN 64
#define FN 256
#define TN 4000
#define FQ (TN / 4)          // 1000 float4 per row
#define THREADS 256

__global__ __launch_bounds__(THREADS)
void mvn_kernel(const float* __restrict__ x,
                const float* __restrict__ lengths,
                float* __restrict__ out) {
    const int row = blockIdx.x;            // b * FN + f
    const int b   = row >> 8;              // FN = 256
    const int tid = threadIdx.x;

    const float4* __restrict__ xr =
        reinterpret_cast<const float4*>(x + (long long)row * TN);
    float4* __restrict__ orow =
        reinterpret_cast<float4*>(out + (long long)row * TN);

    const float nf = rintf(__ldg(&lengths[b]) * (float)TN);  // round-half-even, matches jnp.round
    const int   ni = (int)nf;

    // ---- load row into registers, masked accumulate sum / sumsq ----
    float4 v[4];
    float s  = 0.0f;
    float ss = 0.0f;

    #pragma unroll
    for (int k = 0; k < 4; k++) {
        const int i4 = tid + k * THREADS;
        if (i4 < FQ) {
            v[k] = xr[i4];
            const int t0 = i4 * 4;
            if (t0 + 3 < ni) {
                // fully inside mask (common case)
                s  += v[k].x + v[k].y + v[k].z + v[k].w;
                ss += v[k].x * v[k].x + v[k].y * v[k].y
                    + v[k].z * v[k].z + v[k].w * v[k].w;
            } else if (t0 < ni) {
                // straddles the mask boundary
                if (t0 + 0 < ni) { s += v[k].x; ss += v[k].x * v[k].x; }
                if (t0 + 1 < ni) { s += v[k].y; ss += v[k].y * v[k].y; }
                if (t0 + 2 < ni) { s += v[k].z; ss += v[k].z * v[k].z; }
                if (t0 + 3 < ni) { s += v[k].w; ss += v[k].w * v[k].w; }
            }
        }
    }

    // ---- block reduction: warp shuffle then smem across 8 warps ----
    #pragma unroll
    for (int off = 16; off > 0; off >>= 1) {
        s  += __shfl_xor_sync(0xFFFFFFFFu, s,  off);
        ss += __shfl_xor_sync(0xFFFFFFFFu, ss, off);
    }

    __shared__ float red_s[8];
    __shared__ float red_ss[8];
    __shared__ float bc_mean, bc_istd;

    const int wid  = tid >> 5;
    const int lane = tid & 31;
    if (lane == 0) { red_s[wid] = s; red_ss[wid] = ss; }
    __syncthreads();

    if (tid == 0) {
        float sum = 0.0f, sumsq = 0.0f;
        #pragma unroll
        for (int w = 0; w < 8; w++) { sum += red_s[w]; sumsq += red_ss[w]; }
        const float mean = sum / nf;
        float var = (sumsq - nf * mean * mean) / (nf - 1.0f);
        var = fmaxf(var, 0.0f);
        const float stdv = fmaxf(sqrtf(var), 1e-10f);
        bc_mean = mean;
        bc_istd = 1.0f / stdv;
    }
    __syncthreads();

    const float mean = bc_mean;
    const float istd = bc_istd;

    // ---- normalize entire row from registers, vector store ----
    #pragma unroll
    for (int k = 0; k < 4; k++) {
        const int i4 = tid + k * THREADS;
        if (i4 < FQ) {
            float4 o;
            o.x = (v[k].x - mean) * istd;
            o.y = (v[k].y - mean) * istd;
            o.z = (v[k].z - mean) * istd;
            o.w = (v[k].w - mean) * istd;
            orow[i4] = o;
        }
    }
}

extern "C" void kernel_launch(void* const* d_in, const int* in_sizes, int n_in,
                              void* d_out, int out_size) {
    const float* x       = (const float*)d_in[0];
    const float* lengths = (const float*)d_in[1];
    float* out           = (float*)d_out;

    mvn_kernel<<<BN * FN, THREADS>>>(x, lengths, out);
}

// round 2
// speedup vs baseline: 1.1246x; 1.1246x over previous
#include <cuda_runtime.h>

// mean_var_norm — (B=64, F=256, T=4000) fp32, masked per-row mean/var then
// normalize whole row. Single-pass, 2 rows per CTA software-pipelined:
// all 8 float4 loads (rows A+B) issued up front so row B's loads are in
// flight during row A's reduction bubble. Streaming cache hints (no reuse).

#define BN 64
#define FN 256
#define TN 4000
#define FQ (TN / 4)          // 1000 float4 per row
#define THREADS 256

__global__ __launch_bounds__(THREADS)
void mvn_kernel(const float* __restrict__ x,
                const float* __restrict__ lengths,
                float* __restrict__ out) {
    const int rowA = blockIdx.x * 2;       // rows 2r, 2r+1 — same b (FN even)
    const int b    = rowA >> 8;            // FN = 256
    const int tid  = threadIdx.x;

    const float4* __restrict__ xa =
        reinterpret_cast<const float4*>(x + (long long)rowA * TN);
    const float4* __restrict__ xb = xa + FQ;
    float4* __restrict__ oa =
        reinterpret_cast<float4*>(out + (long long)rowA * TN);
    float4* __restrict__ ob = oa + FQ;

    const float nf = rintf(__ldg(&lengths[b]) * (float)TN);  // matches jnp.round
    const int   ni = (int)nf;

    // ---- issue ALL loads (both rows) up front: 8 outstanding LDG.128 ----
    float4 va[4], vb[4];
    #pragma unroll
    for (int k = 0; k < 4; k++) {
        const int i4 = tid + k * THREADS;
        if (i4 < FQ) va[k] = __ldcs(&xa[i4]);
    }
    #pragma unroll
    for (int k = 0; k < 4; k++) {
        const int i4 = tid + k * THREADS;
        if (i4 < FQ) vb[k] = __ldcs(&xb[i4]);
    }

    __shared__ float red_s[8];
    __shared__ float red_ss[8];
    __shared__ float bc_mean, bc_istd;
    const int wid  = tid >> 5;
    const int lane = tid & 31;

    // ================= process one row (macro-style via loop) =============
    #pragma unroll
    for (int r = 0; r < 2; r++) {
        float4* v = (r == 0) ? va : vb;
        float4* __restrict__ orow = (r == 0) ? oa : ob;

        float s = 0.0f, ss = 0.0f;
        #pragma unroll
        for (int k = 0; k < 4; k++) {
            const int i4 = tid + k * THREADS;
            if (i4 < FQ) {
                const int t0 = i4 * 4;
                if (t0 + 3 < ni) {
                    s  += v[k].x + v[k].y + v[k].z + v[k].w;
                    ss += v[k].x * v[k].x + v[k].y * v[k].y
                        + v[k].z * v[k].z + v[k].w * v[k].w;
                } else if (t0 < ni) {
                    if (t0 + 0 < ni) { s += v[k].x; ss += v[k].x * v[k].x; }
                    if (t0 + 1 < ni) { s += v[k].y; ss += v[k].y * v[k].y; }
                    if (t0 + 2 < ni) { s += v[k].z; ss += v[k].z * v[k].z; }
                    if (t0 + 3 < ni) { s += v[k].w; ss += v[k].w * v[k].w; }
                }
            }
        }

        #pragma unroll
        for (int off = 16; off > 0; off >>= 1) {
            s  += __shfl_xor_sync(0xFFFFFFFFu, s,  off);
            ss += __shfl_xor_sync(0xFFFFFFFFu, ss, off);
        }
        if (lane == 0) { red_s[wid] = s; red_ss[wid] = ss; }
        __syncthreads();

        if (tid == 0) {
            float sum = 0.0f, sumsq = 0.0f;
            #pragma unroll
            for (int w = 0; w < 8; w++) { sum += red_s[w]; sumsq += red_ss[w]; }
            const float mean = sum / nf;
            float var = (sumsq - nf * mean * mean) / (nf - 1.0f);
            var = fmaxf(var, 0.0f);
            bc_mean = mean;
            bc_istd = 1.0f / fmaxf(sqrtf(var), 1e-10f);
        }
        __syncthreads();

        const float mean = bc_mean;
        const float istd = bc_istd;

        #pragma unroll
        for (int k = 0; k < 4; k++) {
            const int i4 = tid + k * THREADS;
            if (i4 < FQ) {
                float4 o;
                o.x = (v[k].x - mean) * istd;
                o.y = (v[k].y - mean) * istd;
                o.z = (v[k].z - mean) * istd;
                o.w = (v[k].w - mean) * istd;
                __stcs(&orow[i4], o);
            }
        }
        // next iteration reuses red_s/red_ss: safe — the second __syncthreads
        // above guarantees tid0 has consumed them before they're rewritten.
        __syncthreads();
    }
}

extern "C" void kernel_launch(void* const* d_in, const int* in_sizes, int n_in,
                              void* d_out, int out_size) {
    const float* x       = (const float*)d_in[0];
    const float* lengths = (const float*)d_in[1];
    float* out           = (float*)d_out;

    mvn_kernel<<<(BN * FN) / 2, THREADS>>>(x, lengths, out);
}

// round 3
// speedup vs baseline: 1.1341x; 1.0084x over previous
#include <cuda_runtime.h>

// mean_var_norm — (B=64, F=256, T=4000) fp32.
// 2 rows per CTA, 512 threads, 2 float4 per row per thread.
// Single merged reduction phase for both rows (2 syncthreads total);
// all 8 outstanding LDG.128 cover the one reduce bubble. Streaming hints.

#define BN 64
#define FN 256
#define TN 4000
#define FQ (TN / 4)          // 1000 float4 per row
#define THREADS 512
#define NW (THREADS / 32)    // 16 warps

__global__ __launch_bounds__(THREADS)
void mvn_kernel(const float* __restrict__ x,
                const float* __restrict__ lengths,
                float* __restrict__ out) {
    const int rowA = blockIdx.x * 2;       // rows 2r, 2r+1 — same b (FN even)
    const int b    = rowA >> 8;            // FN = 256
    const int tid  = threadIdx.x;

    const float4* __restrict__ xa =
        reinterpret_cast<const float4*>(x + (long long)rowA * TN);
    const float4* __restrict__ xb = xa + FQ;
    float4* __restrict__ oa =
        reinterpret_cast<float4*>(out + (long long)rowA * TN);
    float4* __restrict__ ob = oa + FQ;

    const float nf = rintf(__ldg(&lengths[b]) * (float)TN);  // matches jnp.round
    const int   ni = (int)nf;

    // ---- issue ALL loads (both rows) up front ----
    float4 va[2], vb[2];
    #pragma unroll
    for (int k = 0; k < 2; k++) {
        const int i4 = tid + k * THREADS;
        if (i4 < FQ) va[k] = __ldcs(&xa[i4]);
    }
    #pragma unroll
    for (int k = 0; k < 2; k++) {
        const int i4 = tid + k * THREADS;
        if (i4 < FQ) vb[k] = __ldcs(&xb[i4]);
    }

    // ---- masked accumulate BOTH rows ----
    float sA = 0.0f, ssA = 0.0f, sB = 0.0f, ssB = 0.0f;
    #pragma unroll
    for (int k = 0; k < 2; k++) {
        const int i4 = tid + k * THREADS;
        if (i4 < FQ) {
            const int t0 = i4 * 4;
            if (t0 + 3 < ni) {
                sA  += va[k].x + va[k].y + va[k].z + va[k].w;
                ssA += va[k].x * va[k].x + va[k].y * va[k].y
                     + va[k].z * va[k].z + va[k].w * va[k].w;
                sB  += vb[k].x + vb[k].y + vb[k].z + vb[k].w;
                ssB += vb[k].x * vb[k].x + vb[k].y * vb[k].y
                     + vb[k].z * vb[k].z + vb[k].w * vb[k].w;
            } else if (t0 < ni) {
                if (t0 + 0 < ni) { sA += va[k].x; ssA += va[k].x * va[k].x;
                                   sB += vb[k].x; ssB += vb[k].x * vb[k].x; }
                if (t0 + 1 < ni) { sA += va[k].y; ssA += va[k].y * va[k].y;
                                   sB += vb[k].y; ssB += vb[k].y * vb[k].y; }
                if (t0 + 2 < ni) { sA += va[k].z; ssA += va[k].z * va[k].z;
                                   sB += vb[k].z; ssB += vb[k].z * vb[k].z; }
                if (t0 + 3 < ni) { sA += va[k].w; ssA += va[k].w * va[k].w;
                                   sB += vb[k].w; ssB += vb[k].w * vb[k].w; }
            }
        }
    }

    // ---- single merged block reduction (4 values) ----
    #pragma unroll
    for (int off = 16; off > 0; off >>= 1) {
        sA  += __shfl_xor_sync(0xFFFFFFFFu, sA,  off);
        ssA += __shfl_xor_sync(0xFFFFFFFFu, ssA, off);
        sB  += __shfl_xor_sync(0xFFFFFFFFu, sB,  off);
        ssB += __shfl_xor_sync(0xFFFFFFFFu, ssB, off);
    }

    __shared__ float red[4][NW];
    __shared__ float bc[4];                // meanA, istdA, meanB, istdB
    const int wid  = tid >> 5;
    const int lane = tid & 31;
    if (lane == 0) {
        red[0][wid] = sA; red[1][wid] = ssA;
        red[2][wid] = sB; red[3][wid] = ssB;
    }
    __syncthreads();

    if (tid < 2) {
        // tid 0 -> row A, tid 1 -> row B
        float sum = 0.0f, sumsq = 0.0f;
        #pragma unroll
        for (int w = 0; w < NW; w++) {
            sum   += red[2 * tid + 0][w];
            sumsq += red[2 * tid + 1][w];
        }
        const float mean = sum / nf;
        float var = (sumsq - nf * mean * mean) / (nf - 1.0f);
        var = fmaxf(var, 0.0f);
        bc[2 * tid + 0] = mean;
        bc[2 * tid + 1] = 1.0f / fmaxf(sqrtf(var), 1e-10f);
    }
    __syncthreads();

    const float meanA = bc[0], istdA = bc[1];
    const float meanB = bc[2], istdB = bc[3];

    // ---- normalize both rows from registers, vector stores ----
    #pragma unroll
    for (int k = 0; k < 2; k++) {
        const int i4 = tid + k * THREADS;
        if (i4 < FQ) {
            float4 o;
            o.x = (va[k].x - meanA) * istdA;
            o.y = (va[k].y - meanA) * istdA;
            o.z = (va[k].z - meanA) * istdA;
            o.w = (va[k].w - meanA) * istdA;
            __stcs(&oa[i4], o);
            float4 p;
            p.x = (vb[k].x - meanB) * istdB;
            p.y = (vb[k].y - meanB) * istdB;
            p.z = (vb[k].z - meanB) * istdB;
            p.w = (vb[k].w - meanB) * istdB;
            __stcs(&ob[i4], p);
        }
    }
}

extern "C" void kernel_launch(void* const* d_in, const int* in_sizes, int n_in,
                              void* d_out, int out_size) {
    const float* x       = (const float*)d_in[0];
    const float* lengths = (const float*)d_in[1];
    float* out           = (float*)d_out;

    mvn_kernel<<<(BN * FN) / 2, THREADS>>>(x, lengths, out);
}